// round 1
// baseline (speedup 1.0000x reference)
#include <cuda_runtime.h>
#include <cuda_bf16.h>
#include <math_constants.h>

// Problem constants (fixed by the reference)
#define H_FULL 1080
#define W_FULL 1920
#define SC     8
#define H_OUT  (H_FULL / SC)   // 135
#define W_OUT  (W_FULL / SC)   // 240
#define NPIX   (H_OUT * W_OUT) // 32400
#define EPS_A  1e-8f
#define Z_CLIP 0.01f

#define MAXF 4096
// Per-face record, 4 x float4:
//  [0] = (x2-x1, y2-y1, x0-x2, y0-y2)
//  [1] = (x1-x0, y1-y0, x0,    y0   )
//  [2] = (x1,    y1,    x2,    y2   )
//  [3] = (z0,    z1,    z2,    inv  )
__device__ float4 g_face[MAXF * 4];

__device__ __forceinline__ void project_v(float vx, float vy, float vz,
                                          float& xn, float& yn) {
    // x = -vx ; xs = FX*x/z + CX ; ys = FY*y/z + CY
    float x = -vx;
    float xs = 1000.0f * x  / vz + 960.0f;
    float ys = 1000.0f * vy / vz + 540.0f;
    // s = min(H_FULL, W_FULL) = 1080
    xn = -(2.0f * xs - 1920.0f) / 1080.0f;
    yn = -(2.0f * ys - 1080.0f) / 1080.0f;
}

__global__ void face_setup_kernel(const float* __restrict__ verts,
                                  const int*   __restrict__ faces,
                                  int F) {
    int f = blockIdx.x * blockDim.x + threadIdx.x;
    if (f >= F) return;

    int i0 = faces[3 * f + 0];
    int i1 = faces[3 * f + 1];
    int i2 = faces[3 * f + 2];

    float v0x = verts[3 * i0 + 0], v0y = verts[3 * i0 + 1], v0z = verts[3 * i0 + 2];
    float v1x = verts[3 * i1 + 0], v1y = verts[3 * i1 + 1], v1z = verts[3 * i1 + 2];
    float v2x = verts[3 * i2 + 0], v2y = verts[3 * i2 + 1], v2z = verts[3 * i2 + 2];

    float x0, y0, x1, y1, x2, y2;
    project_v(v0x, v0y, v0z, x0, y0);
    project_v(v1x, v1y, v1z, x1, y1);
    project_v(v2x, v2y, v2z, x2, y2);

    float area = (x1 - x0) * (y2 - y0) - (y1 - y0) * (x2 - x0);
    float inv  = (fabsf(area) > EPS_A) ? (1.0f / area) : 0.0f;
    // reference also requires all tz > Z_CLIP; folding into inv=0 forces
    // zp=0 <= Z_CLIP -> face rejected, identical outcome.
    if (!(v0z > Z_CLIP && v1z > Z_CLIP && v2z > Z_CLIP)) inv = 0.0f;

    g_face[f * 4 + 0] = make_float4(x2 - x1, y2 - y1, x0 - x2, y0 - y2);
    g_face[f * 4 + 1] = make_float4(x1 - x0, y1 - y0, x0, y0);
    g_face[f * 4 + 2] = make_float4(x1, y1, x2, y2);
    g_face[f * 4 + 3] = make_float4(v0z, v1z, v2z, inv);
}

#define TILE 256
#define BLOCK 128

__global__ __launch_bounds__(BLOCK)
void raster_kernel(float* __restrict__ out, int F) {
    __shared__ float4 sf[TILE * 4];

    int p = blockIdx.x * blockDim.x + threadIdx.x;
    bool active = (p < NPIX);

    float px = 0.0f, py = 0.0f;
    if (active) {
        int r_out = p / W_OUT;          // output row (flipped)
        int c     = p - r_out * W_OUT;  // column
        int h     = H_OUT - 1 - r_out;  // grid row before the [::-1] flip
        // s = min(H_OUT, W_OUT) = 135
        px = -(2.0f * (float)c + 1.0f - (float)W_OUT) / 135.0f;
        py = -(2.0f * (float)h + 1.0f - (float)H_OUT) / 135.0f;
    }

    float zbest = CUDART_INF_F;
    int   fbest = -1;
    float bb0 = -1.0f, bb1 = -1.0f, bb2 = -1.0f;

    for (int base = 0; base < F; base += TILE) {
        int n = F - base;
        if (n > TILE) n = TILE;

        __syncthreads();
        for (int j = threadIdx.x; j < n * 4; j += BLOCK) {
            sf[j] = g_face[base * 4 + j];
        }
        __syncthreads();

        if (active) {
            #pragma unroll 4
            for (int j = 0; j < n; j++) {
                float4 A = sf[j * 4 + 0];
                float4 B = sf[j * 4 + 1];
                float4 C = sf[j * 4 + 2];
                float4 D = sf[j * 4 + 3];

                // edge(a,b) = (bx-ax)*(py-ay) - (by-ay)*(px-ax)
                float w0 = A.x * (py - C.y) - A.y * (px - C.x); // edge(v1,v2)
                float w1 = A.z * (py - C.w) - A.w * (px - C.z); // edge(v2,v0)
                float w2 = B.x * (py - B.w) - B.y * (px - B.z); // edge(v0,v1)

                float inv = D.w;
                float b0 = w0 * inv;
                float b1 = w1 * inv;
                float b2 = w2 * inv;
                float zp = b0 * D.x + b1 * D.y + b2 * D.z;

                bool valid = (b0 >= 0.0f) & (b1 >= 0.0f) & (b2 >= 0.0f) &
                             (zp > Z_CLIP);
                if (valid && zp < zbest) {
                    zbest = zp;
                    fbest = base + j;
                    bb0 = b0; bb1 = b1; bb2 = b2;
                }
            }
        }
    }

    if (active) {
        out[p] = (float)fbest;
        float* bary = out + NPIX + 3 * p;
        bary[0] = bb0;
        bary[1] = bb1;
        bary[2] = bb2;
    }
}

extern "C" void kernel_launch(void* const* d_in, const int* in_sizes, int n_in,
                              void* d_out, int out_size) {
    const float* verts = (const float*)d_in[0];
    const int*   faces = (const int*)d_in[1];
    int F = in_sizes[1] / 3;
    if (F > MAXF) F = MAXF;

    face_setup_kernel<<<(F + 255) / 256, 256>>>(verts, faces, F);
    raster_kernel<<<(NPIX + BLOCK - 1) / BLOCK, BLOCK>>>((float*)d_out, F);
}

// round 2
// speedup vs baseline: 2.4073x; 2.4073x over previous
#include <cuda_runtime.h>
#include <cuda_bf16.h>
#include <math_constants.h>

#define H_OUT  135
#define W_OUT  240
#define NPIX   (H_OUT * W_OUT)   // 32400
#define EPS_A  1e-8f
#define Z_CLIP 0.01f

#define MAXF   4096
#define NSPLIT 8
#define PPT    4                  // pixels per thread (same row, stride 60)
#define CSTRIDE (W_OUT / PPT)     // 60
#define NTHREADS (H_OUT * CSTRIDE) // 8100
#define SBLOCK 128
#define NPB    ((NTHREADS + SBLOCK - 1) / SBLOCK)  // 64 pixel-blocks

// Per-face folded coefficients, 3 x float4:
//  C0 = (gx0, gy0, k0, gx1)
//  C1 = (gy1, k1, gx2, gy2)
//  C2 = (k2,  zx,  zy,  zk)
// b_i = gx_i*px + gy_i*py + k_i ;  zp = zx*px + zy*py + zk
__device__ float4 g_c[MAXF * 3];
__device__ float  g_sz[NSPLIT][NPIX];
__device__ int    g_sf[NSPLIT][NPIX];

__device__ __forceinline__ void project_v(float vx, float vy, float vz,
                                          float& xn, float& yn) {
    float xs = 1000.0f * (-vx) / vz + 960.0f;
    float ys = 1000.0f * vy    / vz + 540.0f;
    xn = -(2.0f * xs - 1920.0f) / 1080.0f;
    yn = -(2.0f * ys - 1080.0f) / 1080.0f;
}

// identical pixel-coordinate computation used by split AND merge kernels
__device__ __forceinline__ float pix_x(int c) {
    return -(2.0f * (float)c + 1.0f - (float)W_OUT) / 135.0f;
}
__device__ __forceinline__ float pix_y(int r_out) {
    int h = H_OUT - 1 - r_out;   // undo the [::-1] row flip
    return -(2.0f * (float)h + 1.0f - (float)H_OUT) / 135.0f;
}

__global__ void face_setup_kernel(const float* __restrict__ verts,
                                  const int*   __restrict__ faces,
                                  int F) {
    int f = blockIdx.x * blockDim.x + threadIdx.x;
    if (f >= F) return;

    int i0 = faces[3 * f + 0];
    int i1 = faces[3 * f + 1];
    int i2 = faces[3 * f + 2];

    float v0z = verts[3 * i0 + 2];
    float v1z = verts[3 * i1 + 2];
    float v2z = verts[3 * i2 + 2];

    float x0, y0, x1, y1, x2, y2;
    project_v(verts[3 * i0], verts[3 * i0 + 1], v0z, x0, y0);
    project_v(verts[3 * i1], verts[3 * i1 + 1], v1z, x1, y1);
    project_v(verts[3 * i2], verts[3 * i2 + 1], v2z, x2, y2);

    float area = (x1 - x0) * (y2 - y0) - (y1 - y0) * (x2 - x0);
    bool ok = (fabsf(area) > EPS_A) &&
              (v0z > Z_CLIP) && (v1z > Z_CLIP) && (v2z > Z_CLIP);

    if (!ok) {
        // b0 == -1 everywhere -> never valid
        g_c[f * 3 + 0] = make_float4(0.0f, 0.0f, -1.0f, 0.0f);
        g_c[f * 3 + 1] = make_float4(0.0f, 0.0f, 0.0f, 0.0f);
        g_c[f * 3 + 2] = make_float4(0.0f, 0.0f, 0.0f, 0.0f);
        return;
    }

    double inv = (double)(1.0f / area);   // fp32 reciprocal like reference, fold in fp64
    // w0 = edge(v1,v2), w1 = edge(v2,v0), w2 = edge(v0,v1); b_i = w_i*inv
    double gx0 = -(double)(y2 - y1) * inv;
    double gy0 =  (double)(x2 - x1) * inv;
    double k0  = ((double)(y2 - y1) * x1 - (double)(x2 - x1) * y1) * inv;
    double gx1 = -(double)(y0 - y2) * inv;
    double gy1 =  (double)(x0 - x2) * inv;
    double k1  = ((double)(y0 - y2) * x2 - (double)(x0 - x2) * y2) * inv;
    double gx2 = -(double)(y1 - y0) * inv;
    double gy2 =  (double)(x1 - x0) * inv;
    double k2  = ((double)(y1 - y0) * x0 - (double)(x1 - x0) * y0) * inv;

    double zx = gx0 * v0z + gx1 * v1z + gx2 * v2z;
    double zy = gy0 * v0z + gy1 * v1z + gy2 * v2z;
    double zk = k0  * v0z + k1  * v1z + k2  * v2z;

    g_c[f * 3 + 0] = make_float4((float)gx0, (float)gy0, (float)k0, (float)gx1);
    g_c[f * 3 + 1] = make_float4((float)gy1, (float)k1, (float)gx2, (float)gy2);
    g_c[f * 3 + 2] = make_float4((float)k2, (float)zx, (float)zy, (float)zk);
}

__global__ __launch_bounds__(SBLOCK)
void raster_split_kernel(int F, int flen) {
    __shared__ float4 sc[3 * ((MAXF + NSPLIT - 1) / NSPLIT)];

    int s     = blockIdx.y;
    int fbeg  = s * flen;
    int fend  = min(fbeg + flen, F);
    int n     = fend - fbeg;

    // stage this split's face coeffs
    for (int j = threadIdx.x; j < n * 3; j += SBLOCK)
        sc[j] = g_c[fbeg * 3 + j];
    __syncthreads();

    int T = blockIdx.x * SBLOCK + threadIdx.x;
    if (T >= NTHREADS) return;
    int row = T / CSTRIDE;
    int c0  = T - row * CSTRIDE;

    float py = pix_y(row);
    float px0 = pix_x(c0);
    float px1 = pix_x(c0 + CSTRIDE);
    float px2 = pix_x(c0 + 2 * CSTRIDE);
    float px3 = pix_x(c0 + 3 * CSTRIDE);

    float z0 = CUDART_INF_F, z1 = CUDART_INF_F, z2 = CUDART_INF_F, z3 = CUDART_INF_F;
    int   f0 = -1, f1 = -1, f2 = -1, f3 = -1;

    #pragma unroll 2
    for (int j = 0; j < n; j++) {
        float4 A = sc[j * 3 + 0];
        float4 B = sc[j * 3 + 1];
        float4 C = sc[j * 3 + 2];

        float t0 = fmaf(A.y, py, A.z);   // gy0*py + k0
        float t1 = fmaf(B.x, py, B.y);   // gy1*py + k1
        float t2 = fmaf(B.w, py, C.x);   // gy2*py + k2
        float tz = fmaf(C.z, py, C.w);   // zy*py + zk
        int   gf = fbeg + j;

        {
            float b0 = fmaf(A.x, px0, t0);
            float b1 = fmaf(A.w, px0, t1);
            float b2 = fmaf(B.z, px0, t2);
            float zp = fmaf(C.y, px0, tz);
            float m  = fminf(fminf(b0, b1), b2);
            if (m >= 0.0f && zp < z0) { z0 = zp; f0 = gf; }
        }
        {
            float b0 = fmaf(A.x, px1, t0);
            float b1 = fmaf(A.w, px1, t1);
            float b2 = fmaf(B.z, px1, t2);
            float zp = fmaf(C.y, px1, tz);
            float m  = fminf(fminf(b0, b1), b2);
            if (m >= 0.0f && zp < z1) { z1 = zp; f1 = gf; }
        }
        {
            float b0 = fmaf(A.x, px2, t0);
            float b1 = fmaf(A.w, px2, t1);
            float b2 = fmaf(B.z, px2, t2);
            float zp = fmaf(C.y, px2, tz);
            float m  = fminf(fminf(b0, b1), b2);
            if (m >= 0.0f && zp < z2) { z2 = zp; f2 = gf; }
        }
        {
            float b0 = fmaf(A.x, px3, t0);
            float b1 = fmaf(A.w, px3, t1);
            float b2 = fmaf(B.z, px3, t2);
            float zp = fmaf(C.y, px3, tz);
            float m  = fminf(fminf(b0, b1), b2);
            if (m >= 0.0f && zp < z3) { z3 = zp; f3 = gf; }
        }
    }

    int p = row * W_OUT + c0;
    g_sz[s][p]                = z0;  g_sf[s][p]                = f0;
    g_sz[s][p + CSTRIDE]      = z1;  g_sf[s][p + CSTRIDE]      = f1;
    g_sz[s][p + 2 * CSTRIDE]  = z2;  g_sf[s][p + 2 * CSTRIDE]  = f2;
    g_sz[s][p + 3 * CSTRIDE]  = z3;  g_sf[s][p + 3 * CSTRIDE]  = f3;
}

__global__ __launch_bounds__(128)
void merge_kernel(float* __restrict__ out) {
    int p = blockIdx.x * blockDim.x + threadIdx.x;
    if (p >= NPIX) return;

    float zb = CUDART_INF_F;
    int   fb = -1;
    // ascending split order + strict '<'  ==  global lowest-index tie-break
    #pragma unroll
    for (int s = 0; s < NSPLIT; s++) {
        float z = g_sz[s][p];
        int   f = g_sf[s][p];
        if (z < zb) { zb = z; fb = f; }
    }

    float bb0 = -1.0f, bb1 = -1.0f, bb2 = -1.0f;
    if (fb >= 0) {
        float4 A = g_c[fb * 3 + 0];
        float4 B = g_c[fb * 3 + 1];

        int row = p / W_OUT;
        int c   = p - row * W_OUT;
        float py = pix_y(row);
        float px = pix_x(c);

        // identical op order to the split kernel -> identical values
        float t0 = fmaf(A.y, py, A.z);
        float t1 = fmaf(B.x, py, B.y);
        float t2 = fmaf(B.w, py, g_c[fb * 3 + 2].x);
        bb0 = fmaf(A.x, px, t0);
        bb1 = fmaf(A.w, px, t1);
        bb2 = fmaf(B.z, px, t2);
    }

    out[p] = (float)fb;
    float* bary = out + NPIX + 3 * p;
    bary[0] = bb0;
    bary[1] = bb1;
    bary[2] = bb2;
}

extern "C" void kernel_launch(void* const* d_in, const int* in_sizes, int n_in,
                              void* d_out, int out_size) {
    const float* verts = (const float*)d_in[0];
    const int*   faces = (const int*)d_in[1];
    int F = in_sizes[1] / 3;
    if (F > MAXF) F = MAXF;
    int flen = (F + NSPLIT - 1) / NSPLIT;

    face_setup_kernel<<<(F + 255) / 256, 256>>>(verts, faces, F);
    raster_split_kernel<<<dim3(NPB, NSPLIT), SBLOCK>>>(F, flen);
    merge_kernel<<<(NPIX + 127) / 128, 128>>>((float*)d_out);
}

// round 3
// speedup vs baseline: 3.9532x; 1.6421x over previous
#include <cuda_runtime.h>
#include <cuda_bf16.h>
#include <math_constants.h>

#define H_OUT  135
#define W_OUT  240
#define NPIX   (H_OUT * W_OUT)   // 32400
#define EPS_A  1e-8f
#define Z_CLIP 0.01f

#define MAXF   4096
#define NSPLIT 16
#define FLEN_MAX ((MAXF + NSPLIT - 1) / NSPLIT)   // 256
#define ROWS_PER_BLOCK 4
#define NBLK_ROW ((H_OUT + ROWS_PER_BLOCK - 1) / ROWS_PER_BLOCK)  // 34
#define KPT 8    // pixels per lane (cols lane, lane+32, ..., lane+224)

// Per-face folded coefficients, 3 x float4:
//  C0 = (gx0, gy0, k0, gx1)
//  C1 = (gy1, k1, gx2, gy2)
//  C2 = (k2,  zx,  zy,  zk)
// b_i = gx_i*px + gy_i*py + k_i ;  zp = zx*px + zy*py + zk
__device__ float4 g_c[MAXF * 3];
__device__ float2 g_bd[MAXF];               // (ymin-eps, ymax+eps), (+inf,-inf) if dead
__device__ float2 g_szf[NSPLIT][NPIX];      // (z, face-bits)

__device__ __forceinline__ void project_v(float vx, float vy, float vz,
                                          float& xn, float& yn) {
    float xs = 1000.0f * (-vx) / vz + 960.0f;
    float ys = 1000.0f * vy    / vz + 540.0f;
    xn = -(2.0f * xs - 1920.0f) / 1080.0f;
    yn = -(2.0f * ys - 1080.0f) / 1080.0f;
}

__device__ __forceinline__ float pix_x(int c) {
    return -(2.0f * (float)c + 1.0f - (float)W_OUT) / 135.0f;
}
__device__ __forceinline__ float pix_y(int r_out) {
    int h = H_OUT - 1 - r_out;   // undo the [::-1] row flip
    return -(2.0f * (float)h + 1.0f - (float)H_OUT) / 135.0f;
}

__global__ void face_setup_kernel(const float* __restrict__ verts,
                                  const int*   __restrict__ faces,
                                  int F) {
    int f = blockIdx.x * blockDim.x + threadIdx.x;
    if (f >= F) return;

    int i0 = faces[3 * f + 0];
    int i1 = faces[3 * f + 1];
    int i2 = faces[3 * f + 2];

    float v0z = verts[3 * i0 + 2];
    float v1z = verts[3 * i1 + 2];
    float v2z = verts[3 * i2 + 2];

    float x0, y0, x1, y1, x2, y2;
    project_v(verts[3 * i0], verts[3 * i0 + 1], v0z, x0, y0);
    project_v(verts[3 * i1], verts[3 * i1 + 1], v1z, x1, y1);
    project_v(verts[3 * i2], verts[3 * i2 + 1], v2z, x2, y2);

    float area = (x1 - x0) * (y2 - y0) - (y1 - y0) * (x2 - x0);
    bool ok = (fabsf(area) > EPS_A) &&
              (v0z > Z_CLIP) && (v1z > Z_CLIP) && (v2z > Z_CLIP);

    if (!ok) {
        g_c[f * 3 + 0] = make_float4(0.0f, 0.0f, -1.0f, 0.0f);
        g_c[f * 3 + 1] = make_float4(0.0f, 0.0f, 0.0f, 0.0f);
        g_c[f * 3 + 2] = make_float4(0.0f, 0.0f, 0.0f, 0.0f);
        g_bd[f] = make_float2(CUDART_INF_F, -CUDART_INF_F);  // never passes cull
        return;
    }

    double inv = (double)(1.0f / area);   // fp32 reciprocal like reference, fold in fp64
    double gx0 = -(double)(y2 - y1) * inv;
    double gy0 =  (double)(x2 - x1) * inv;
    double k0  = ((double)(y2 - y1) * x1 - (double)(x2 - x1) * y1) * inv;
    double gx1 = -(double)(y0 - y2) * inv;
    double gy1 =  (double)(x0 - x2) * inv;
    double k1  = ((double)(y0 - y2) * x2 - (double)(x0 - x2) * y2) * inv;
    double gx2 = -(double)(y1 - y0) * inv;
    double gy2 =  (double)(x1 - x0) * inv;
    double k2  = ((double)(y1 - y0) * x0 - (double)(x1 - x0) * y0) * inv;

    double zx = gx0 * v0z + gx1 * v1z + gx2 * v2z;
    double zy = gy0 * v0z + gy1 * v1z + gy2 * v2z;
    double zk = k0  * v0z + k1  * v1z + k2  * v2z;

    g_c[f * 3 + 0] = make_float4((float)gx0, (float)gy0, (float)k0, (float)gx1);
    g_c[f * 3 + 1] = make_float4((float)gy1, (float)k1, (float)gx2, (float)gy2);
    g_c[f * 3 + 2] = make_float4((float)k2, (float)zx, (float)zy, (float)zk);

    float ymin = fminf(y0, fminf(y1, y2)) - 2e-6f;
    float ymax = fmaxf(y0, fmaxf(y1, y2)) + 2e-6f;
    g_bd[f] = make_float2(ymin, ymax);
}

__global__ __launch_bounds__(128)
void raster_split_kernel(int F, int flen) {
    __shared__ float4 sc[FLEN_MAX * 3];
    __shared__ float2 sbd[FLEN_MAX];
    __shared__ int    slist[4][FLEN_MAX];

    int s    = blockIdx.y;
    int fbeg = s * flen;
    int n    = F - fbeg;
    if (n > flen) n = flen;
    if (n < 0) n = 0;

    for (int j = threadIdx.x; j < n * 3; j += 128) sc[j]  = g_c[fbeg * 3 + j];
    for (int j = threadIdx.x; j < n;     j += 128) sbd[j] = g_bd[fbeg + j];
    __syncthreads();

    int wid  = threadIdx.x >> 5;
    int lane = threadIdx.x & 31;
    int row  = blockIdx.x * ROWS_PER_BLOCK + wid;
    bool rowok = (row < H_OUT);
    float py = pix_y(rowok ? row : 0);

    // warp-uniform y-cull -> compacted ascending face list (per warp)
    int nlist = 0;
    for (int g = 0; g < n; g += 32) {
        int f = g + lane;
        bool pass = false;
        if (f < n) {
            float2 bd = sbd[f];
            pass = (py >= bd.x) && (py <= bd.y);
        }
        unsigned m = __ballot_sync(0xffffffffu, pass);
        if (pass) slist[wid][nlist + __popc(m & ((1u << lane) - 1u))] = f;
        nlist += __popc(m);
    }

    float px[KPT], z[KPT];
    int fb[KPT];
    #pragma unroll
    for (int k = 0; k < KPT; k++) {
        px[k] = pix_x(lane + 32 * k);
        z[k] = CUDART_INF_F;
        fb[k] = -1;
    }

    for (int j = 0; j < nlist; j++) {
        int f = slist[wid][j];
        float4 A = sc[f * 3 + 0];
        float4 B = sc[f * 3 + 1];
        float4 C = sc[f * 3 + 2];

        float t0 = fmaf(A.y, py, A.z);   // gy0*py + k0
        float t1 = fmaf(B.x, py, B.y);   // gy1*py + k1
        float t2 = fmaf(B.w, py, C.x);   // gy2*py + k2
        float tz = fmaf(C.z, py, C.w);   // zy*py + zk
        int   gf = fbeg + f;

        #pragma unroll
        for (int k = 0; k < KPT; k++) {
            float b0 = fmaf(A.x, px[k], t0);
            float b1 = fmaf(A.w, px[k], t1);
            float b2 = fmaf(B.z, px[k], t2);
            float zp = fmaf(C.y, px[k], tz);
            float mm = fminf(fminf(b0, b1), b2);
            if (mm >= 0.0f && zp < z[k]) { z[k] = zp; fb[k] = gf; }
        }
    }

    if (rowok) {
        int pbase = row * W_OUT;
        #pragma unroll
        for (int k = 0; k < KPT; k++) {
            int c = lane + 32 * k;
            if (c < W_OUT)
                g_szf[s][pbase + c] = make_float2(z[k], __int_as_float(fb[k]));
        }
    }
}

__global__ __launch_bounds__(256)
void merge_kernel(float* __restrict__ out) {
    int p = blockIdx.x * blockDim.x + threadIdx.x;
    if (p >= NPIX) return;

    float zb = CUDART_INF_F;
    int   fb = -1;
    // ascending split order + strict '<'  ==  global lowest-index tie-break
    #pragma unroll
    for (int s = 0; s < NSPLIT; s++) {
        float2 v = g_szf[s][p];
        if (v.x < zb) { zb = v.x; fb = __float_as_int(v.y); }
    }

    float bb0 = -1.0f, bb1 = -1.0f, bb2 = -1.0f;
    if (fb >= 0) {
        float4 A = g_c[fb * 3 + 0];
        float4 B = g_c[fb * 3 + 1];
        float k2 = g_c[fb * 3 + 2].x;

        int row = p / W_OUT;
        int c   = p - row * W_OUT;
        float py = pix_y(row);
        float px = pix_x(c);

        float t0 = fmaf(A.y, py, A.z);
        float t1 = fmaf(B.x, py, B.y);
        float t2 = fmaf(B.w, py, k2);
        bb0 = fmaf(A.x, px, t0);
        bb1 = fmaf(A.w, px, t1);
        bb2 = fmaf(B.z, px, t2);
    }

    out[p] = (float)fb;
    float* bary = out + NPIX + 3 * p;
    bary[0] = bb0;
    bary[1] = bb1;
    bary[2] = bb2;
}

extern "C" void kernel_launch(void* const* d_in, const int* in_sizes, int n_in,
                              void* d_out, int out_size) {
    const float* verts = (const float*)d_in[0];
    const int*   faces = (const int*)d_in[1];
    int F = in_sizes[1] / 3;
    if (F > MAXF) F = MAXF;
    int flen = (F + NSPLIT - 1) / NSPLIT;

    face_setup_kernel<<<(F + 127) / 128, 128>>>(verts, faces, F);
    raster_split_kernel<<<dim3(NBLK_ROW, NSPLIT), 128>>>(F, flen);
    merge_kernel<<<(NPIX + 255) / 256, 256>>>((float*)d_out);
}